// round 15
// baseline (speedup 1.0000x reference)
#include <cuda_runtime.h>
#include <cuda_fp16.h>
#include <cstdint>

#define NHEADS 16
#define DK     64
#define DM     1024
#define NB     2
#define SEQ    2048
#define MTOT   (NB*SEQ)   /* 4096 */
#define NBH    (NB*NHEADS)

typedef __half fp16;

// scratch (__device__ globals; no allocs allowed)
static __device__ fp16  g_X [3][(size_t)MTOT*DM];       // X fp16 (q,k,v)
static __device__ fp16  g_W [4][(size_t)DM*DM];         // W^T fp16 (q,k,v,hidden)
static __device__ fp16  g_Q [(size_t)NBH*SEQ*DK];       // per-head [bh][s][d]
static __device__ fp16  g_K [(size_t)NBH*SEQ*DK];
static __device__ fp16  g_Vp[(size_t)NBH*SEQ*DK];       // V per-head [bh][s][d]
static __device__ fp16  g_H [(size_t)MTOT*DM];          // Hc fp16

// ---------------------------------------------------------------------------
__device__ __forceinline__ uint32_t smem_u32(const void* p) {
    uint32_t a;
    asm("{ .reg .u64 t; cvta.to.shared.u64 t, %1; cvt.u32.u64 %0, t; }"
        : "=r"(a) : "l"(p));
    return a;
}
#define CP16(dst, src) \
    asm volatile("cp.async.cg.shared.global [%0], [%1], 16;" \
        :: "r"(dst), "l"(src) : "memory")
#define CPCOMMIT() asm volatile("cp.async.commit_group;" ::: "memory")
#define CPWAIT(n)  asm volatile("cp.async.wait_group %0;" :: "n"(n) : "memory")

#define LDSM4(d, addr) \
    asm volatile("ldmatrix.sync.aligned.m8n8.x4.shared.b16 {%0,%1,%2,%3}, [%4];" \
        : "=r"((d)[0]), "=r"((d)[1]), "=r"((d)[2]), "=r"((d)[3]) : "r"(addr))

#define LDSM4T(d, addr) \
    asm volatile("ldmatrix.sync.aligned.m8n8.x4.trans.shared.b16 {%0,%1,%2,%3}, [%4];" \
        : "=r"((d)[0]), "=r"((d)[1]), "=r"((d)[2]), "=r"((d)[3]) : "r"(addr))

#define MMA_FP16(c, a, b0v, b1v) \
    asm volatile("mma.sync.aligned.m16n8k16.row.col.f32.f16.f16.f32 " \
        "{%0,%1,%2,%3},{%4,%5,%6,%7},{%8,%9},{%0,%1,%2,%3};" \
        : "+f"((c)[0]), "+f"((c)[1]), "+f"((c)[2]), "+f"((c)[3]) \
        : "r"((a)[0]), "r"((a)[1]), "r"((a)[2]), "r"((a)[3]), "r"(b0v), "r"(b1v))

__device__ __forceinline__ uint32_t pack2(float a, float b) {
    __half2 h = __floats2half2_rn(a, b);   // a -> low, b -> high
    return *reinterpret_cast<uint32_t*>(&h);
}
// sigmoid(v/8) = 0.5 + 0.5*tanh(v/16)  — single MUFU op per element
__device__ __forceinline__ float sigm(float v) {
    float t;
    asm("tanh.approx.f32 %0, %1;" : "=f"(t) : "f"(v * 0.0625f));
    return fmaf(0.5f, t, 0.5f);
}

// ---------------------------------------------------------------------------
// prep kernels (merged)
// ---------------------------------------------------------------------------
__global__ void cvt_x3(const float4* __restrict__ s0, const float4* __restrict__ s1,
                       const float4* __restrict__ s2, uint2* __restrict__ dst)
{
    const int z = blockIdx.y;
    const float4* src = (z == 0) ? s0 : (z == 1) ? s1 : s2;
    const int i = blockIdx.x * 256 + threadIdx.x;
    const float4 v = src[i];
    dst[(size_t)z * ((size_t)MTOT * DM / 4) + i] =
        make_uint2(pack2(v.x, v.y), pack2(v.z, v.w));
}

__global__ void wtrans4(const float* __restrict__ w0, const float* __restrict__ w1,
                        const float* __restrict__ w2, const float* __restrict__ w3,
                        fp16* __restrict__ dstbase)
{
    __shared__ float t[32][33];
    const int z = blockIdx.z;
    const float* src = (z == 0) ? w0 : (z == 1) ? w1 : (z == 2) ? w2 : w3;
    fp16* dst = dstbase + (size_t)z * DM * DM;
    int x = blockIdx.x * 32 + threadIdx.x;
    int y = blockIdx.y * 32 + threadIdx.y;
    #pragma unroll
    for (int j = 0; j < 32; j += 8)
        t[threadIdx.y + j][threadIdx.x] = src[(long long)(y + j) * DM + x];
    __syncthreads();
    x = blockIdx.y * 32 + threadIdx.x;
    y = blockIdx.x * 32 + threadIdx.y;
    #pragma unroll
    for (int j = 0; j < 32; j += 8)
        dst[(long long)(y + j) * DM + x] = __float2half_rn(t[threadIdx.x][threadIdx.y + j]);
}

// ---------------------------------------------------------------------------
// GEMM core shared by QKV-projection and out-projection.
// C[M,1024] = A[M,1024] @ B[1024,1024]^T. BM=BN=128, chunk 64 k, 8 warps.
// ---------------------------------------------------------------------------
template<typename EpiFn>
__device__ __forceinline__ void gemm_core(
    const fp16* __restrict__ A, const fp16* __restrict__ B,
    int m0, int n0, char* smp, EpiFn epi)
{
    constexpr int TSZ = 128 * 144;
    constexpr int STG = 2 * TSZ;
    const int tid = threadIdx.x, lane = tid & 31, wid = tid >> 5;
    const int wm0 = (wid & 1) * 64, wn0 = (wid >> 1) * 32;
    const uint32_t sb = smem_u32(smp);

    auto issue = [&](int kt) {
        const uint32_t st = sb + (kt & 1) * STG;
        const long long kof = (long long)kt * 64;
        #pragma unroll
        for (int i = 0; i < 4; ++i) {
            const int c = tid + i * 256, row = c >> 3, col = c & 7;
            const uint32_t d = st + row * 144 + col * 16;
            CP16(d,       A + (long long)(m0 + row) * DM + kof + col * 8);
            CP16(d + TSZ, B + (long long)(n0 + row) * DM + kof + col * 8);
        }
        CPCOMMIT();
    };

    float acc[4][4][4] = {};
    const int frow = lane & 15, fk8 = (lane >> 4) * 8;

    issue(0);
    issue(1);
    for (int kt = 0; kt < 16; ++kt) {
        if (kt < 15) CPWAIT(1); else CPWAIT(0);
        __syncthreads();
        const uint32_t st = sb + (kt & 1) * STG;
        #pragma unroll
        for (int kq = 0; kq < 4; ++kq) {
            uint32_t af[4][4], bf2[2][4];
            #pragma unroll
            for (int mg = 0; mg < 4; ++mg) {
                const uint32_t off = ((wm0 + mg * 16 + frow) * 72 + kq * 16 + fk8) * 2;
                LDSM4(af[mg], st + off);
            }
            #pragma unroll
            for (int nn = 0; nn < 2; ++nn) {
                const uint32_t off = ((wn0 + nn * 16 + frow) * 72 + kq * 16 + fk8) * 2;
                LDSM4(bf2[nn], st + TSZ + off);
            }
            #pragma unroll
            for (int mg = 0; mg < 4; ++mg)
                #pragma unroll
                for (int nn = 0; nn < 2; ++nn)
                    #pragma unroll
                    for (int g = 0; g < 2; ++g)
                        MMA_FP16(acc[mg][nn * 2 + g], af[mg], bf2[nn][g], bf2[nn][g + 2]);
        }
        __syncthreads();
        if (kt + 2 < 16) issue(kt + 2);
    }

    #pragma unroll
    for (int mg = 0; mg < 4; ++mg) {
        const int row = m0 + wm0 + mg * 16 + (lane >> 2);
        #pragma unroll
        for (int n8 = 0; n8 < 4; ++n8) {
            const int col = n0 + wn0 + n8 * 8 + (lane & 3) * 2;
            epi(row, col, acc[mg][n8]);
        }
    }
}

// Q/K/V projections in one launch: z in {0,1,2}, all write per-head fp16
__global__ __launch_bounds__(256, 2) void pgemm_qkv(
    const fp16* __restrict__ X, const fp16* __restrict__ W,
    fp16* __restrict__ Qp, fp16* __restrict__ Kp, fp16* __restrict__ Vp)
{
    extern __shared__ char smp[];
    const int z = blockIdx.z;
    const fp16* A = X + (size_t)z * MTOT * DM;
    const fp16* B = W + (size_t)z * DM * DM;
    const int m0 = blockIdx.y * 128, n0 = blockIdx.x * 128;
    fp16* Ch = (z == 0) ? Qp : (z == 1) ? Kp : Vp;
    gemm_core(A, B, m0, n0, smp,
        [&](int row, int col, float* v) {
            const int bh = ((row >> 11) << 4) + (col >> 6);
            const int s = row & 2047, d = col & 63;
            const size_t off = ((size_t)bh * SEQ + s) * DK + d;
            *reinterpret_cast<uint32_t*>(Ch + off)          = pack2(v[0], v[1]);
            *reinterpret_cast<uint32_t*>(Ch + off + 8 * DK) = pack2(v[2], v[3]);
        });
}

// out-projection (+bias)
__global__ __launch_bounds__(256, 2) void pgemm_out(
    const fp16* __restrict__ A, const fp16* __restrict__ B,
    float* __restrict__ Cf, const float* __restrict__ bias)
{
    extern __shared__ char smp[];
    const int m0 = blockIdx.y * 128, n0 = blockIdx.x * 128;
    gemm_core(A, B, m0, n0, smp,
        [&](int row, int col, float* v) {
            const float b0 = bias[col], b1 = bias[col + 1];
            *reinterpret_cast<float2*>(Cf + (long long)row * DM + col) =
                make_float2(v[0] + b0, v[1] + b1);
            *reinterpret_cast<float2*>(Cf + (long long)(row + 8) * DM + col) =
                make_float2(v[2] + b0, v[3] + b1);
        });
}

// ---------------------------------------------------------------------------
// fused attention v4: Q-tile 64, 256 threads, 2 CTAs/SM. A-store is staged
// through the DEAD K-region of the current stage (K frags fully consumed by
// S-MMA), swizzled (ch + 5*row)&31, then written as full 512B rows with
// STG.128 -> 128B wavefronts instead of 32B ones.
// warps: wm 0..3 (16 S-rows), wn 0..1 (64 S-cols = split-k half for H)
// ---------------------------------------------------------------------------
__global__ __launch_bounds__(256, 2) void fused_attn(
    const fp16* __restrict__ Q, const fp16* __restrict__ K,
    const fp16* __restrict__ V,
    float* __restrict__ Aout, fp16* __restrict__ Hp)
{
    extern __shared__ char smf[];
    constexpr int KT   = 144;               // Q/K/V smem row bytes (64 fp16 + pad)
    constexpr int QSZ  = 64 * KT;           // 9216
    constexpr int KSZ  = 128 * KT;          // 18432
    constexpr int BUFS = 2 * KSZ;           // K|V per stage = 36864
    constexpr int NT   = SEQ / 128;         // 16

    const int tid = threadIdx.x, lane = tid & 31, wid = tid >> 5;
    const int wm = wid & 3, wn = wid >> 2;
    const int bh = blockIdx.y, b = bh >> 4, h = bh & 15;
    const int q0 = blockIdx.x * 64;
    const uint32_t sb = smem_u32(smf);
    const int frow = lane & 15, fk8 = (lane >> 4) * 8;

    // Q tile (once): 64 rows x 8 16B-chunks = 512 chunks, 256 threads
    {
        const fp16* Qg = Q + ((size_t)bh * SEQ + q0) * DK;
        #pragma unroll
        for (int i = 0; i < 2; ++i) {
            const int c = tid + i * 256, row = c >> 3, col = c & 7;
            CP16(sb + row * KT + col * 16, Qg + row * DK + col * 8);
        }
        CPCOMMIT();
    }

    auto issue = [&](int kt) {
        const uint32_t st = sb + QSZ + (kt & 1) * BUFS;
        const fp16* kg = K + ((size_t)bh * SEQ + kt * 128) * DK;
        const fp16* vg = V + ((size_t)bh * SEQ + kt * 128) * DK;
        #pragma unroll
        for (int i = 0; i < 4; ++i) {      // 128 rows x 8 chunks each
            const int c = tid + i * 256, row = c >> 3, col = c & 7;
            CP16(st + row * KT + col * 16,       kg + row * DK + col * 8);
            CP16(st + KSZ + row * KT + col * 16, vg + row * DK + col * 8);
        }
        CPCOMMIT();
    };
    issue(0);
    issue(1);

    float accH[8][4] = {};
    float* Abase = Aout + (size_t)bh * SEQ * SEQ;

    // per-lane base for trans V loads: tile order (k0n0, k0n8, k8n0, k8n8)
    const uint32_t vlrow = ((lane >> 4) << 3) + (lane & 7);   // k within 16
    const uint32_t vlcol = ((lane >> 3) & 1) * 16;            // n*2 bytes

    const int myp = wm >> 1;               // staging pass this warp writes in

    for (int kt = 0; kt < NT; ++kt) {
        if (kt + 1 < NT) CPWAIT(1); else CPWAIT(0);
        __syncthreads();
        const uint32_t st = sb + QSZ + (kt & 1) * BUFS;

        // ---- S = Q @ K^T (16 rows x 64 cols per warp) ----
        float accS[8][4] = {};
        #pragma unroll
        for (int kq = 0; kq < 4; ++kq) {
            uint32_t qf[4], kf[4][4];
            {
                const uint32_t off = ((wm * 16 + frow) * 72 + kq * 16 + fk8) * 2;
                LDSM4(qf, sb + off);
            }
            #pragma unroll
            for (int nn = 0; nn < 4; ++nn) {
                const uint32_t off = ((wn * 64 + nn * 16 + frow) * 72 + kq * 16 + fk8) * 2;
                LDSM4(kf[nn], st + off);
            }
            #pragma unroll
            for (int nn = 0; nn < 4; ++nn)
                #pragma unroll
                for (int g = 0; g < 2; ++g)
                    MMA_FP16(accS[nn * 2 + g], qf, kf[nn][g], kf[nn][g + 2]);
        }

        // ---- sigmoid (single-MUFU tanh form) ----
        #pragma unroll
        for (int n8 = 0; n8 < 8; ++n8)
            #pragma unroll
            for (int e = 0; e < 4; ++e)
                accS[n8][e] = sigm(accS[n8][e]);

        // ---- in-register A fragments (acc -> A-frag identity) ----
        uint32_t af[4][4];
        #pragma unroll
        for (int j = 0; j < 4; ++j) {
            af[j][0] = pack2(accS[2 * j][0],     accS[2 * j][1]);
            af[j][1] = pack2(accS[2 * j][2],     accS[2 * j][3]);
            af[j][2] = pack2(accS[2 * j + 1][0], accS[2 * j + 1][1]);
            af[j][3] = pack2(accS[2 * j + 1][2], accS[2 * j + 1][3]);
        }

        // ---- staged A store through dead K-region (coalesced STG.128) ----
        #pragma unroll
        for (int p = 0; p < 2; ++p) {
            __syncthreads();   // p0: K frag reads done; p1: prior readback done
            if (myp == p) {
                const int rl0 = (wm & 1) * 16 + (lane >> 2);
                const int chb = wn * 16 + ((lane & 3) >> 1);
                const int hb  = ((lane & 3) & 1) * 8;
                #pragma unroll
                for (int n8 = 0; n8 < 8; ++n8) {
                    const int ch = chb + n8 * 2;
                    const uint32_t a0 = st + rl0 * 512 +
                        (((ch + 5 * rl0) & 31) << 4) + hb;
                    asm volatile("st.shared.v2.f32 [%0], {%1,%2};"
                                 :: "r"(a0), "f"(accS[n8][0]), "f"(accS[n8][1])
                                 : "memory");
                    const int rl1 = rl0 + 8;
                    const uint32_t a1 = st + rl1 * 512 +
                        (((ch + 5 * rl1) & 31) << 4) + hb;
                    asm volatile("st.shared.v2.f32 [%0], {%1,%2};"
                                 :: "r"(a1), "f"(accS[n8][2]), "f"(accS[n8][3])
                                 : "memory");
                }
            }
            __syncthreads();
            // readback + coalesced store: 4 full rows (512B) per warp
            #pragma unroll
            for (int i = 0; i < 4; ++i) {
                const int rloc = wid * 4 + i;
                const uint32_t la = st + rloc * 512 +
                    (((lane + 5 * rloc) & 31) << 4);
                float4 v;
                asm volatile("ld.shared.v4.f32 {%0,%1,%2,%3}, [%4];"
                             : "=f"(v.x), "=f"(v.y), "=f"(v.z), "=f"(v.w)
                             : "r"(la));
                const int grow = p * 32 + rloc;
                __stcs(reinterpret_cast<float4*>(
                           Abase + (size_t)(q0 + grow) * SEQ + kt * 128) + lane, v);
            }
        }

        // ---- H += S @ V over this warp's 64-row (s) k-slice ----
        #pragma unroll
        for (int j = 0; j < 4; ++j) {
            const uint32_t vbase =
                st + KSZ + (wn * 64 + j * 16 + vlrow) * KT + vlcol;
            uint32_t vf[4][4];
            #pragma unroll
            for (int vn = 0; vn < 4; ++vn)
                LDSM4T(vf[vn], vbase + vn * 32);
            #pragma unroll
            for (int vn = 0; vn < 4; ++vn)
                #pragma unroll
                for (int g = 0; g < 2; ++g)
                    MMA_FP16(accH[vn * 2 + g], af[j], vf[vn][g], vf[vn][g + 2]);
        }

        __syncthreads();                   // stage kt consumed; safe to refill
        if (kt + 2 < NT) issue(kt + 2);
    }

    // ---- split-k reduce (wn=1 into wn=0) + write Hc fp16 ----
    __syncthreads();
    float* red = reinterpret_cast<float*>(smf);   // 64 x 66 fp32 (tiles dead)
    const int rl = wm * 16 + (lane >> 2);
    if (wn == 1) {
        #pragma unroll
        for (int n8 = 0; n8 < 8; ++n8) {
            const int col = n8 * 8 + (lane & 3) * 2;
            *reinterpret_cast<float2*>(&red[(size_t)rl * 66 + col]) =
                make_float2(accH[n8][0], accH[n8][1]);
            *reinterpret_cast<float2*>(&red[(size_t)(rl + 8) * 66 + col]) =
                make_float2(accH[n8][2], accH[n8][3]);
        }
    }
    __syncthreads();
    if (wn == 0) {
        #pragma unroll
        for (int n8 = 0; n8 < 8; ++n8) {
            const int col = n8 * 8 + (lane & 3) * 2;
            const float2 p0 = *reinterpret_cast<float2*>(&red[(size_t)rl * 66 + col]);
            const float2 p1 = *reinterpret_cast<float2*>(&red[(size_t)(rl + 8) * 66 + col]);
            const size_t off = ((size_t)(b * SEQ + q0 + rl)) * DM + h * DK + col;
            *reinterpret_cast<uint32_t*>(Hp + off) =
                pack2(accH[n8][0] + p0.x, accH[n8][1] + p0.y);
            *reinterpret_cast<uint32_t*>(Hp + off + 8 * DM) =
                pack2(accH[n8][2] + p1.x, accH[n8][3] + p1.y);
        }
    }
}

// ---------------------------------------------------------------------------
extern "C" void kernel_launch(void* const* d_in, const int* in_sizes, int n_in,
                              void* d_out, int out_size)
{
    (void)in_sizes; (void)n_in; (void)out_size;
    const float* Xq = (const float*)d_in[0];
    const float* Xk = (const float*)d_in[1];
    const float* Xv = (const float*)d_in[2];
    const float* Wq = (const float*)d_in[3];
    const float* Wk = (const float*)d_in[4];
    const float* Wv = (const float*)d_in[5];
    const float* Wh = (const float*)d_in[6];
    const float* bh = (const float*)d_in[7];

    float* out  = (float*)d_out;
    float* Aout = out + (size_t)MTOT * DM;

    fp16 *xp, *wp, *qp, *kp, *vp, *hp;
    cudaGetSymbolAddress((void**)&xp, g_X);
    cudaGetSymbolAddress((void**)&wp, g_W);
    cudaGetSymbolAddress((void**)&qp, g_Q);
    cudaGetSymbolAddress((void**)&kp, g_K);
    cudaGetSymbolAddress((void**)&vp, g_Vp);
    cudaGetSymbolAddress((void**)&hp, g_H);

    const size_t WN = (size_t)DM * DM;
    const int smP = 2 * 2 * 128 * 144;             // 73728
    const int smF = 64 * 144 + 2 * 2 * 128 * 144;  // 82944 (2 CTAs/SM)
    cudaFuncSetAttribute(pgemm_qkv, cudaFuncAttributeMaxDynamicSharedMemorySize, smP);
    cudaFuncSetAttribute(pgemm_out, cudaFuncAttributeMaxDynamicSharedMemorySize, smP);
    cudaFuncSetAttribute(fused_attn, cudaFuncAttributeMaxDynamicSharedMemorySize, smF);

    // prep: W^T fp16 (one launch), X fp16 (one launch)
    wtrans4<<<dim3(32, 32, 4), dim3(32, 8)>>>(Wq, Wk, Wv, Wh, wp);
    cvt_x3<<<dim3(4096, 3), 256>>>((const float4*)Xq, (const float4*)Xk,
                                   (const float4*)Xv, (uint2*)xp);

    // Q/K/V projections in one launch (all per-head fp16)
    pgemm_qkv<<<dim3(DM / 128, MTOT / 128, 3), 256, smP>>>(xp, wp, qp, kp, vp);

    // fused attention (writes A fp32 and Hc fp16); Q-tile 64 -> grid (32, 32)
    fused_attn<<<dim3(SEQ / 64, NBH), 256, smF>>>(qp, kp, vp, Aout, hp);

    // output projection (+bias)
    pgemm_out<<<dim3(DM / 128, MTOT / 128), 256, smP>>>(hp, wp + 3 * WN, out, bh);
}

// round 16
// speedup vs baseline: 1.0404x; 1.0404x over previous
#include <cuda_runtime.h>
#include <cuda_fp16.h>
#include <cstdint>

#define NHEADS 16
#define DK     64
#define DM     1024
#define NB     2
#define SEQ    2048
#define MTOT   (NB*SEQ)   /* 4096 */
#define NBH    (NB*NHEADS)

typedef __half fp16;

// scratch (__device__ globals; no allocs allowed)
static __device__ fp16  g_X [3][(size_t)MTOT*DM];       // X fp16 (q,k,v)
static __device__ fp16  g_W [4][(size_t)DM*DM];         // W^T fp16 (q,k,v,hidden)
static __device__ fp16  g_Q [(size_t)NBH*SEQ*DK];       // per-head [bh][s][d]
static __device__ fp16  g_K [(size_t)NBH*SEQ*DK];
static __device__ fp16  g_Vp[(size_t)NBH*SEQ*DK];       // V per-head [bh][s][d]
static __device__ fp16  g_H [(size_t)MTOT*DM];          // Hc fp16

// ---------------------------------------------------------------------------
__device__ __forceinline__ uint32_t smem_u32(const void* p) {
    uint32_t a;
    asm("{ .reg .u64 t; cvta.to.shared.u64 t, %1; cvt.u32.u64 %0, t; }"
        : "=r"(a) : "l"(p));
    return a;
}
#define CP16(dst, src) \
    asm volatile("cp.async.cg.shared.global [%0], [%1], 16;" \
        :: "r"(dst), "l"(src) : "memory")
#define CPCOMMIT() asm volatile("cp.async.commit_group;" ::: "memory")
#define CPWAIT(n)  asm volatile("cp.async.wait_group %0;" :: "n"(n) : "memory")

#define LDSM4(d, addr) \
    asm volatile("ldmatrix.sync.aligned.m8n8.x4.shared.b16 {%0,%1,%2,%3}, [%4];" \
        : "=r"((d)[0]), "=r"((d)[1]), "=r"((d)[2]), "=r"((d)[3]) : "r"(addr))

#define LDSM4T(d, addr) \
    asm volatile("ldmatrix.sync.aligned.m8n8.x4.trans.shared.b16 {%0,%1,%2,%3}, [%4];" \
        : "=r"((d)[0]), "=r"((d)[1]), "=r"((d)[2]), "=r"((d)[3]) : "r"(addr))

#define MMA_FP16(c, a, b0v, b1v) \
    asm volatile("mma.sync.aligned.m16n8k16.row.col.f32.f16.f16.f32 " \
        "{%0,%1,%2,%3},{%4,%5,%6,%7},{%8,%9},{%0,%1,%2,%3};" \
        : "+f"((c)[0]), "+f"((c)[1]), "+f"((c)[2]), "+f"((c)[3]) \
        : "r"((a)[0]), "r"((a)[1]), "r"((a)[2]), "r"((a)[3]), "r"(b0v), "r"(b1v))

__device__ __forceinline__ uint32_t pack2(float a, float b) {
    __half2 h = __floats2half2_rn(a, b);   // a -> low, b -> high
    return *reinterpret_cast<uint32_t*>(&h);
}
// sigmoid(v/8) = 0.5 + 0.5*tanh(v/16)  — single MUFU op per element
__device__ __forceinline__ float sigm(float v) {
    float t;
    asm("tanh.approx.f32 %0, %1;" : "=f"(t) : "f"(v * 0.0625f));
    return fmaf(0.5f, t, 0.5f);
}

// ---------------------------------------------------------------------------
// prep kernels (merged)
// ---------------------------------------------------------------------------
__global__ void cvt_x3(const float4* __restrict__ s0, const float4* __restrict__ s1,
                       const float4* __restrict__ s2, uint2* __restrict__ dst)
{
    const int z = blockIdx.y;
    const float4* src = (z == 0) ? s0 : (z == 1) ? s1 : s2;
    const int i = blockIdx.x * 256 + threadIdx.x;
    const float4 v = src[i];
    dst[(size_t)z * ((size_t)MTOT * DM / 4) + i] =
        make_uint2(pack2(v.x, v.y), pack2(v.z, v.w));
}

__global__ void wtrans4(const float* __restrict__ w0, const float* __restrict__ w1,
                        const float* __restrict__ w2, const float* __restrict__ w3,
                        fp16* __restrict__ dstbase)
{
    __shared__ float t[32][33];
    const int z = blockIdx.z;
    const float* src = (z == 0) ? w0 : (z == 1) ? w1 : (z == 2) ? w2 : w3;
    fp16* dst = dstbase + (size_t)z * DM * DM;
    int x = blockIdx.x * 32 + threadIdx.x;
    int y = blockIdx.y * 32 + threadIdx.y;
    #pragma unroll
    for (int j = 0; j < 32; j += 8)
        t[threadIdx.y + j][threadIdx.x] = src[(long long)(y + j) * DM + x];
    __syncthreads();
    x = blockIdx.y * 32 + threadIdx.x;
    y = blockIdx.x * 32 + threadIdx.y;
    #pragma unroll
    for (int j = 0; j < 32; j += 8)
        dst[(long long)(y + j) * DM + x] = __float2half_rn(t[threadIdx.x][threadIdx.y + j]);
}

// ---------------------------------------------------------------------------
// GEMM core shared by QKV-projection and out-projection.
// C[M,1024] = A[M,1024] @ B[1024,1024]^T. BM=BN=128, chunk 64 k, 8 warps.
// ---------------------------------------------------------------------------
template<typename EpiFn>
__device__ __forceinline__ void gemm_core(
    const fp16* __restrict__ A, const fp16* __restrict__ B,
    int m0, int n0, char* smp, EpiFn epi)
{
    constexpr int TSZ = 128 * 144;
    constexpr int STG = 2 * TSZ;
    const int tid = threadIdx.x, lane = tid & 31, wid = tid >> 5;
    const int wm0 = (wid & 1) * 64, wn0 = (wid >> 1) * 32;
    const uint32_t sb = smem_u32(smp);

    auto issue = [&](int kt) {
        const uint32_t st = sb + (kt & 1) * STG;
        const long long kof = (long long)kt * 64;
        #pragma unroll
        for (int i = 0; i < 4; ++i) {
            const int c = tid + i * 256, row = c >> 3, col = c & 7;
            const uint32_t d = st + row * 144 + col * 16;
            CP16(d,       A + (long long)(m0 + row) * DM + kof + col * 8);
            CP16(d + TSZ, B + (long long)(n0 + row) * DM + kof + col * 8);
        }
        CPCOMMIT();
    };

    float acc[4][4][4] = {};
    const int frow = lane & 15, fk8 = (lane >> 4) * 8;

    issue(0);
    issue(1);
    for (int kt = 0; kt < 16; ++kt) {
        if (kt < 15) CPWAIT(1); else CPWAIT(0);
        __syncthreads();
        const uint32_t st = sb + (kt & 1) * STG;
        #pragma unroll
        for (int kq = 0; kq < 4; ++kq) {
            uint32_t af[4][4], bf2[2][4];
            #pragma unroll
            for (int mg = 0; mg < 4; ++mg) {
                const uint32_t off = ((wm0 + mg * 16 + frow) * 72 + kq * 16 + fk8) * 2;
                LDSM4(af[mg], st + off);
            }
            #pragma unroll
            for (int nn = 0; nn < 2; ++nn) {
                const uint32_t off = ((wn0 + nn * 16 + frow) * 72 + kq * 16 + fk8) * 2;
                LDSM4(bf2[nn], st + TSZ + off);
            }
            #pragma unroll
            for (int mg = 0; mg < 4; ++mg)
                #pragma unroll
                for (int nn = 0; nn < 2; ++nn)
                    #pragma unroll
                    for (int g = 0; g < 2; ++g)
                        MMA_FP16(acc[mg][nn * 2 + g], af[mg], bf2[nn][g], bf2[nn][g + 2]);
        }
        __syncthreads();
        if (kt + 2 < 16) issue(kt + 2);
    }

    #pragma unroll
    for (int mg = 0; mg < 4; ++mg) {
        const int row = m0 + wm0 + mg * 16 + (lane >> 2);
        #pragma unroll
        for (int n8 = 0; n8 < 4; ++n8) {
            const int col = n0 + wn0 + n8 * 8 + (lane & 3) * 2;
            epi(row, col, acc[mg][n8]);
        }
    }
}

// Q/K/V projections in one launch: z in {0,1,2}, all write per-head fp16
__global__ __launch_bounds__(256, 2) void pgemm_qkv(
    const fp16* __restrict__ X, const fp16* __restrict__ W,
    fp16* __restrict__ Qp, fp16* __restrict__ Kp, fp16* __restrict__ Vp)
{
    extern __shared__ char smp[];
    const int z = blockIdx.z;
    const fp16* A = X + (size_t)z * MTOT * DM;
    const fp16* B = W + (size_t)z * DM * DM;
    const int m0 = blockIdx.y * 128, n0 = blockIdx.x * 128;
    fp16* Ch = (z == 0) ? Qp : (z == 1) ? Kp : Vp;
    gemm_core(A, B, m0, n0, smp,
        [&](int row, int col, float* v) {
            const int bh = ((row >> 11) << 4) + (col >> 6);
            const int s = row & 2047, d = col & 63;
            const size_t off = ((size_t)bh * SEQ + s) * DK + d;
            *reinterpret_cast<uint32_t*>(Ch + off)          = pack2(v[0], v[1]);
            *reinterpret_cast<uint32_t*>(Ch + off + 8 * DK) = pack2(v[2], v[3]);
        });
}

// out-projection (+bias)
__global__ __launch_bounds__(256, 2) void pgemm_out(
    const fp16* __restrict__ A, const fp16* __restrict__ B,
    float* __restrict__ Cf, const float* __restrict__ bias)
{
    extern __shared__ char smp[];
    const int m0 = blockIdx.y * 128, n0 = blockIdx.x * 128;
    gemm_core(A, B, m0, n0, smp,
        [&](int row, int col, float* v) {
            const float b0 = bias[col], b1 = bias[col + 1];
            *reinterpret_cast<float2*>(Cf + (long long)row * DM + col) =
                make_float2(v[0] + b0, v[1] + b1);
            *reinterpret_cast<float2*>(Cf + (long long)(row + 8) * DM + col) =
                make_float2(v[2] + b0, v[3] + b1);
        });
}

// ---------------------------------------------------------------------------
// fused attention v5 (R14 body + quad-exchange A-store):
//   per tile: S = Q@K^T -> sigmoid(tanh) -> quad-shuffle -> STG.128 A (.cs)
//             -> in-reg A-frags -> H += S@V
// The shuffle gives each quad-lane 4 consecutive floats of its row, halving
// A-store wavefronts (64B useful per 128B wavefront instead of 32B).
// warps: wm 0..3 (16 S-rows), wn 0..1 (64 S-cols = split-k half for H)
// ---------------------------------------------------------------------------
__global__ __launch_bounds__(256, 2) void fused_attn(
    const fp16* __restrict__ Q, const fp16* __restrict__ K,
    const fp16* __restrict__ V,
    float* __restrict__ Aout, fp16* __restrict__ Hp)
{
    extern __shared__ char smf[];
    constexpr int KT   = 144;               // Q/K/V smem row bytes (64 fp16 + pad)
    constexpr int QSZ  = 64 * KT;           // 9216
    constexpr int KSZ  = 128 * KT;          // 18432
    constexpr int BUFS = 2 * KSZ;           // K|V per stage = 36864
    constexpr int NT   = SEQ / 128;         // 16

    const int tid = threadIdx.x, lane = tid & 31, wid = tid >> 5;
    const int wm = wid & 3, wn = wid >> 2;
    const int bh = blockIdx.y, b = bh >> 4, h = bh & 15;
    const int q0 = blockIdx.x * 64;
    const uint32_t sb = smem_u32(smf);
    const int frow = lane & 15, fk8 = (lane >> 4) * 8;

    // Q tile (once): 64 rows x 8 16B-chunks = 512 chunks, 256 threads
    {
        const fp16* Qg = Q + ((size_t)bh * SEQ + q0) * DK;
        #pragma unroll
        for (int i = 0; i < 2; ++i) {
            const int c = tid + i * 256, row = c >> 3, col = c & 7;
            CP16(sb + row * KT + col * 16, Qg + row * DK + col * 8);
        }
        CPCOMMIT();
    }

    auto issue = [&](int kt) {
        const uint32_t st = sb + QSZ + (kt & 1) * BUFS;
        const fp16* kg = K + ((size_t)bh * SEQ + kt * 128) * DK;
        const fp16* vg = V + ((size_t)bh * SEQ + kt * 128) * DK;
        #pragma unroll
        for (int i = 0; i < 4; ++i) {      // 128 rows x 8 chunks each
            const int c = tid + i * 256, row = c >> 3, col = c & 7;
            CP16(st + row * KT + col * 16,       kg + row * DK + col * 8);
            CP16(st + KSZ + row * KT + col * 16, vg + row * DK + col * 8);
        }
        CPCOMMIT();
    };
    issue(0);
    issue(1);

    float accH[8][4] = {};
    float* Abase = Aout + (size_t)bh * SEQ * SEQ;

    // per-lane base for trans V loads: tile order (k0n0, k0n8, k8n0, k8n8)
    const uint32_t vlrow = ((lane >> 4) << 3) + (lane & 7);   // k within 16
    const uint32_t vlcol = ((lane >> 3) & 1) * 16;            // n*2 bytes

    // quad-exchange constants (A-store coalescing)
    const int q4 = lane & 3;
    const int s0 = (lane & ~3) | ((q4 << 1) & 3);   // src for 1st float2
    const int s1 = s0 | 1;                          // src for 2nd float2
    const bool lo = (q4 < 2);                       // take even-n8 else odd-n8

    for (int kt = 0; kt < NT; ++kt) {
        if (kt + 1 < NT) CPWAIT(1); else CPWAIT(0);
        __syncthreads();
        const uint32_t st = sb + QSZ + (kt & 1) * BUFS;

        // ---- S = Q @ K^T (16 rows x 64 cols per warp) ----
        float accS[8][4] = {};
        #pragma unroll
        for (int kq = 0; kq < 4; ++kq) {
            uint32_t qf[4], kf[4][4];
            {
                const uint32_t off = ((wm * 16 + frow) * 72 + kq * 16 + fk8) * 2;
                LDSM4(qf, sb + off);
            }
            #pragma unroll
            for (int nn = 0; nn < 4; ++nn) {
                const uint32_t off = ((wn * 64 + nn * 16 + frow) * 72 + kq * 16 + fk8) * 2;
                LDSM4(kf[nn], st + off);
            }
            #pragma unroll
            for (int nn = 0; nn < 4; ++nn)
                #pragma unroll
                for (int g = 0; g < 2; ++g)
                    MMA_FP16(accS[nn * 2 + g], qf, kf[nn][g], kf[nn][g + 2]);
        }

        // ---- sigmoid (single-MUFU tanh form) ----
        #pragma unroll
        for (int n8 = 0; n8 < 8; ++n8)
            #pragma unroll
            for (int e = 0; e < 4; ++e)
                accS[n8][e] = sigm(accS[n8][e]);

        // ---- quad-exchange + coalesced A store (STG.128, values identical) ----
        #pragma unroll
        for (int t = 0; t < 4; ++t) {
            #pragma unroll
            for (int hh = 0; hh < 2; ++hh) {
                const float ex = accS[2 * t][2 * hh],     ey = accS[2 * t][2 * hh + 1];
                const float ox = accS[2 * t + 1][2 * hh], oy = accS[2 * t + 1][2 * hh + 1];
                const float a0 = __shfl_sync(0xffffffffu, ex, s0);
                const float b0 = __shfl_sync(0xffffffffu, ox, s0);
                const float a1 = __shfl_sync(0xffffffffu, ey, s0);
                const float b1 = __shfl_sync(0xffffffffu, oy, s0);
                const float a2 = __shfl_sync(0xffffffffu, ex, s1);
                const float b2 = __shfl_sync(0xffffffffu, ox, s1);
                const float a3 = __shfl_sync(0xffffffffu, ey, s1);
                const float b3 = __shfl_sync(0xffffffffu, oy, s1);
                const float4 vv = make_float4(lo ? a0 : b0, lo ? a1 : b1,
                                              lo ? a2 : b2, lo ? a3 : b3);
                const int row = q0 + wm * 16 + (lane >> 2) + hh * 8;
                __stcs(reinterpret_cast<float4*>(
                           Abase + (size_t)row * SEQ + kt * 128 + wn * 64 +
                           t * 16 + q4 * 4), vv);
            }
        }

        // ---- in-register A fragments (acc -> A-frag identity) ----
        uint32_t af[4][4];
        #pragma unroll
        for (int j = 0; j < 4; ++j) {
            af[j][0] = pack2(accS[2 * j][0],     accS[2 * j][1]);
            af[j][1] = pack2(accS[2 * j][2],     accS[2 * j][3]);
            af[j][2] = pack2(accS[2 * j + 1][0], accS[2 * j + 1][1]);
            af[j][3] = pack2(accS[2 * j + 1][2], accS[2 * j + 1][3]);
        }

        // ---- H += S @ V over this warp's 64-row (s) k-slice ----
        #pragma unroll
        for (int j = 0; j < 4; ++j) {
            const uint32_t vbase =
                st + KSZ + (wn * 64 + j * 16 + vlrow) * KT + vlcol;
            uint32_t vf[4][4];
            #pragma unroll
            for (int vn = 0; vn < 4; ++vn)
                LDSM4T(vf[vn], vbase + vn * 32);
            #pragma unroll
            for (int vn = 0; vn < 4; ++vn)
                #pragma unroll
                for (int g = 0; g < 2; ++g)
                    MMA_FP16(accH[vn * 2 + g], af[j], vf[vn][g], vf[vn][g + 2]);
        }

        __syncthreads();                   // stage kt consumed; safe to refill
        if (kt + 2 < NT) issue(kt + 2);
    }

    // ---- split-k reduce (wn=1 into wn=0) + write Hc fp16 ----
    __syncthreads();
    float* red = reinterpret_cast<float*>(smf);   // 64 x 66 fp32 (tiles dead)
    const int rl = wm * 16 + (lane >> 2);
    if (wn == 1) {
        #pragma unroll
        for (int n8 = 0; n8 < 8; ++n8) {
            const int col = n8 * 8 + (lane & 3) * 2;
            *reinterpret_cast<float2*>(&red[(size_t)rl * 66 + col]) =
                make_float2(accH[n8][0], accH[n8][1]);
            *reinterpret_cast<float2*>(&red[(size_t)(rl + 8) * 66 + col]) =
                make_float2(accH[n8][2], accH[n8][3]);
        }
    }
    __syncthreads();
    if (wn == 0) {
        #pragma unroll
        for (int n8 = 0; n8 < 8; ++n8) {
            const int col = n8 * 8 + (lane & 3) * 2;
            const float2 p0 = *reinterpret_cast<float2*>(&red[(size_t)rl * 66 + col]);
            const float2 p1 = *reinterpret_cast<float2*>(&red[(size_t)(rl + 8) * 66 + col]);
            const size_t off = ((size_t)(b * SEQ + q0 + rl)) * DM + h * DK + col;
            *reinterpret_cast<uint32_t*>(Hp + off) =
                pack2(accH[n8][0] + p0.x, accH[n8][1] + p0.y);
            *reinterpret_cast<uint32_t*>(Hp + off + 8 * DM) =
                pack2(accH[n8][2] + p1.x, accH[n8][3] + p1.y);
        }
    }
}

// ---------------------------------------------------------------------------
extern "C" void kernel_launch(void* const* d_in, const int* in_sizes, int n_in,
                              void* d_out, int out_size)
{
    (void)in_sizes; (void)n_in; (void)out_size;
    const float* Xq = (const float*)d_in[0];
    const float* Xk = (const float*)d_in[1];
    const float* Xv = (const float*)d_in[2];
    const float* Wq = (const float*)d_in[3];
    const float* Wk = (const float*)d_in[4];
    const float* Wv = (const float*)d_in[5];
    const float* Wh = (const float*)d_in[6];
    const float* bh = (const float*)d_in[7];

    float* out  = (float*)d_out;
    float* Aout = out + (size_t)MTOT * DM;

    fp16 *xp, *wp, *qp, *kp, *vp, *hp;
    cudaGetSymbolAddress((void**)&xp, g_X);
    cudaGetSymbolAddress((void**)&wp, g_W);
    cudaGetSymbolAddress((void**)&qp, g_Q);
    cudaGetSymbolAddress((void**)&kp, g_K);
    cudaGetSymbolAddress((void**)&vp, g_Vp);
    cudaGetSymbolAddress((void**)&hp, g_H);

    const size_t WN = (size_t)DM * DM;
    const int smP = 2 * 2 * 128 * 144;             // 73728
    const int smF = 64 * 144 + 2 * 2 * 128 * 144;  // 82944 (2 CTAs/SM)
    cudaFuncSetAttribute(pgemm_qkv, cudaFuncAttributeMaxDynamicSharedMemorySize, smP);
    cudaFuncSetAttribute(pgemm_out, cudaFuncAttributeMaxDynamicSharedMemorySize, smP);
    cudaFuncSetAttribute(fused_attn, cudaFuncAttributeMaxDynamicSharedMemorySize, smF);

    // prep: W^T fp16 (one launch), X fp16 (one launch)
    wtrans4<<<dim3(32, 32, 4), dim3(32, 8)>>>(Wq, Wk, Wv, Wh, wp);
    cvt_x3<<<dim3(4096, 3), 256>>>((const float4*)Xq, (const float4*)Xk,
                                   (const float4*)Xv, (uint2*)xp);

    // Q/K/V projections in one launch (all per-head fp16)
    pgemm_qkv<<<dim3(DM / 128, MTOT / 128, 3), 256, smP>>>(xp, wp, qp, kp, vp);

    // fused attention (writes A fp32 and Hc fp16); Q-tile 64 -> grid (32, 32)
    fused_attn<<<dim3(SEQ / 64, NBH), 256, smF>>>(qp, kp, vp, Aout, hp);

    // output projection (+bias)
    pgemm_out<<<dim3(DM / 128, MTOT / 128), 256, smP>>>(hp, wp + 3 * WN, out, bh);
}

// round 17
// speedup vs baseline: 1.0856x; 1.0435x over previous
#include <cuda_runtime.h>
#include <cuda_fp16.h>
#include <cstdint>

#define NHEADS 16
#define DK     64
#define DM     1024
#define NB     2
#define SEQ    2048
#define MTOT   (NB*SEQ)   /* 4096 */
#define NBH    (NB*NHEADS)

typedef __half fp16;

// scratch (__device__ globals; no allocs allowed)
static __device__ fp16  g_X [3][(size_t)MTOT*DM];       // X fp16 (q,k,v)
static __device__ fp16  g_W [4][(size_t)DM*DM];         // W^T fp16 (q,k,v,hidden)
static __device__ fp16  g_Q [(size_t)NBH*SEQ*DK];       // per-head [bh][s][d]
static __device__ fp16  g_K [(size_t)NBH*SEQ*DK];
static __device__ fp16  g_Vp[(size_t)NBH*SEQ*DK];       // V per-head [bh][s][d]
static __device__ fp16  g_H [(size_t)MTOT*DM];          // Hc fp16

// ---------------------------------------------------------------------------
__device__ __forceinline__ uint32_t smem_u32(const void* p) {
    uint32_t a;
    asm("{ .reg .u64 t; cvta.to.shared.u64 t, %1; cvt.u32.u64 %0, t; }"
        : "=r"(a) : "l"(p));
    return a;
}
#define CP16(dst, src) \
    asm volatile("cp.async.cg.shared.global [%0], [%1], 16;" \
        :: "r"(dst), "l"(src) : "memory")
#define CPCOMMIT() asm volatile("cp.async.commit_group;" ::: "memory")
#define CPWAIT(n)  asm volatile("cp.async.wait_group %0;" :: "n"(n) : "memory")

#define LDSM4(d, addr) \
    asm volatile("ldmatrix.sync.aligned.m8n8.x4.shared.b16 {%0,%1,%2,%3}, [%4];" \
        : "=r"((d)[0]), "=r"((d)[1]), "=r"((d)[2]), "=r"((d)[3]) : "r"(addr))

#define LDSM4T(d, addr) \
    asm volatile("ldmatrix.sync.aligned.m8n8.x4.trans.shared.b16 {%0,%1,%2,%3}, [%4];" \
        : "=r"((d)[0]), "=r"((d)[1]), "=r"((d)[2]), "=r"((d)[3]) : "r"(addr))

#define MMA_FP16(c, a, b0v, b1v) \
    asm volatile("mma.sync.aligned.m16n8k16.row.col.f32.f16.f16.f32 " \
        "{%0,%1,%2,%3},{%4,%5,%6,%7},{%8,%9},{%0,%1,%2,%3};" \
        : "+f"((c)[0]), "+f"((c)[1]), "+f"((c)[2]), "+f"((c)[3]) \
        : "r"((a)[0]), "r"((a)[1]), "r"((a)[2]), "r"((a)[3]), "r"(b0v), "r"(b1v))

__device__ __forceinline__ uint32_t pack2(float a, float b) {
    __half2 h = __floats2half2_rn(a, b);   // a -> low, b -> high
    return *reinterpret_cast<uint32_t*>(&h);
}
// sigmoid(v/8) = 0.5 + 0.5*tanh(v/16)  — single MUFU op per element
__device__ __forceinline__ float sigm(float v) {
    float t;
    asm("tanh.approx.f32 %0, %1;" : "=f"(t) : "f"(v * 0.0625f));
    return fmaf(0.5f, t, 0.5f);
}

// ---------------------------------------------------------------------------
// prep kernels (merged)
// ---------------------------------------------------------------------------
__global__ void cvt_x3(const float4* __restrict__ s0, const float4* __restrict__ s1,
                       const float4* __restrict__ s2, uint2* __restrict__ dst)
{
    const int z = blockIdx.y;
    const float4* src = (z == 0) ? s0 : (z == 1) ? s1 : s2;
    const int i = blockIdx.x * 256 + threadIdx.x;
    const float4 v = src[i];
    dst[(size_t)z * ((size_t)MTOT * DM / 4) + i] =
        make_uint2(pack2(v.x, v.y), pack2(v.z, v.w));
}

__global__ void wtrans4(const float* __restrict__ w0, const float* __restrict__ w1,
                        const float* __restrict__ w2, const float* __restrict__ w3,
                        fp16* __restrict__ dstbase)
{
    __shared__ float t[32][33];
    const int z = blockIdx.z;
    const float* src = (z == 0) ? w0 : (z == 1) ? w1 : (z == 2) ? w2 : w3;
    fp16* dst = dstbase + (size_t)z * DM * DM;
    int x = blockIdx.x * 32 + threadIdx.x;
    int y = blockIdx.y * 32 + threadIdx.y;
    #pragma unroll
    for (int j = 0; j < 32; j += 8)
        t[threadIdx.y + j][threadIdx.x] = src[(long long)(y + j) * DM + x];
    __syncthreads();
    x = blockIdx.y * 32 + threadIdx.x;
    y = blockIdx.x * 32 + threadIdx.y;
    #pragma unroll
    for (int j = 0; j < 32; j += 8)
        dst[(long long)(y + j) * DM + x] = __float2half_rn(t[threadIdx.x][threadIdx.y + j]);
}

// ---------------------------------------------------------------------------
// GEMM core shared by QKV-projection and out-projection.
// C[M,1024] = A[M,1024] @ B[1024,1024]^T. BM=BN=128, chunk 64 k, 8 warps.
// ---------------------------------------------------------------------------
template<typename EpiFn>
__device__ __forceinline__ void gemm_core(
    const fp16* __restrict__ A, const fp16* __restrict__ B,
    int m0, int n0, char* smp, EpiFn epi)
{
    constexpr int TSZ = 128 * 144;
    constexpr int STG = 2 * TSZ;
    const int tid = threadIdx.x, lane = tid & 31, wid = tid >> 5;
    const int wm0 = (wid & 1) * 64, wn0 = (wid >> 1) * 32;
    const uint32_t sb = smem_u32(smp);

    auto issue = [&](int kt) {
        const uint32_t st = sb + (kt & 1) * STG;
        const long long kof = (long long)kt * 64;
        #pragma unroll
        for (int i = 0; i < 4; ++i) {
            const int c = tid + i * 256, row = c >> 3, col = c & 7;
            const uint32_t d = st + row * 144 + col * 16;
            CP16(d,       A + (long long)(m0 + row) * DM + kof + col * 8);
            CP16(d + TSZ, B + (long long)(n0 + row) * DM + kof + col * 8);
        }
        CPCOMMIT();
    };

    float acc[4][4][4] = {};
    const int frow = lane & 15, fk8 = (lane >> 4) * 8;

    issue(0);
    issue(1);
    for (int kt = 0; kt < 16; ++kt) {
        if (kt < 15) CPWAIT(1); else CPWAIT(0);
        __syncthreads();
        const uint32_t st = sb + (kt & 1) * STG;
        #pragma unroll
        for (int kq = 0; kq < 4; ++kq) {
            uint32_t af[4][4], bf2[2][4];
            #pragma unroll
            for (int mg = 0; mg < 4; ++mg) {
                const uint32_t off = ((wm0 + mg * 16 + frow) * 72 + kq * 16 + fk8) * 2;
                LDSM4(af[mg], st + off);
            }
            #pragma unroll
            for (int nn = 0; nn < 2; ++nn) {
                const uint32_t off = ((wn0 + nn * 16 + frow) * 72 + kq * 16 + fk8) * 2;
                LDSM4(bf2[nn], st + TSZ + off);
            }
            #pragma unroll
            for (int mg = 0; mg < 4; ++mg)
                #pragma unroll
                for (int nn = 0; nn < 2; ++nn)
                    #pragma unroll
                    for (int g = 0; g < 2; ++g)
                        MMA_FP16(acc[mg][nn * 2 + g], af[mg], bf2[nn][g], bf2[nn][g + 2]);
        }
        __syncthreads();
        if (kt + 2 < 16) issue(kt + 2);
    }

    #pragma unroll
    for (int mg = 0; mg < 4; ++mg) {
        const int row = m0 + wm0 + mg * 16 + (lane >> 2);
        #pragma unroll
        for (int n8 = 0; n8 < 4; ++n8) {
            const int col = n0 + wn0 + n8 * 8 + (lane & 3) * 2;
            epi(row, col, acc[mg][n8]);
        }
    }
}

// Q/K/V projections in one launch: z in {0,1,2}, all write per-head fp16
__global__ __launch_bounds__(256, 2) void pgemm_qkv(
    const fp16* __restrict__ X, const fp16* __restrict__ W,
    fp16* __restrict__ Qp, fp16* __restrict__ Kp, fp16* __restrict__ Vp)
{
    extern __shared__ char smp[];
    const int z = blockIdx.z;
    const fp16* A = X + (size_t)z * MTOT * DM;
    const fp16* B = W + (size_t)z * DM * DM;
    const int m0 = blockIdx.y * 128, n0 = blockIdx.x * 128;
    fp16* Ch = (z == 0) ? Qp : (z == 1) ? Kp : Vp;
    gemm_core(A, B, m0, n0, smp,
        [&](int row, int col, float* v) {
            const int bh = ((row >> 11) << 4) + (col >> 6);
            const int s = row & 2047, d = col & 63;
            const size_t off = ((size_t)bh * SEQ + s) * DK + d;
            *reinterpret_cast<uint32_t*>(Ch + off)          = pack2(v[0], v[1]);
            *reinterpret_cast<uint32_t*>(Ch + off + 8 * DK) = pack2(v[2], v[3]);
        });
}

// out-projection (+bias)
__global__ __launch_bounds__(256, 2) void pgemm_out(
    const fp16* __restrict__ A, const fp16* __restrict__ B,
    float* __restrict__ Cf, const float* __restrict__ bias)
{
    extern __shared__ char smp[];
    const int m0 = blockIdx.y * 128, n0 = blockIdx.x * 128;
    gemm_core(A, B, m0, n0, smp,
        [&](int row, int col, float* v) {
            const float b0 = bias[col], b1 = bias[col + 1];
            *reinterpret_cast<float2*>(Cf + (long long)row * DM + col) =
                make_float2(v[0] + b0, v[1] + b1);
            *reinterpret_cast<float2*>(Cf + (long long)(row + 8) * DM + col) =
                make_float2(v[2] + b0, v[3] + b1);
        });
}

// ---------------------------------------------------------------------------
// fused attention v6 (R14 body + 3-stage ring + hoisted Q frags + 1 barrier):
//   per tile: sync -> S-MMA (Q from regs) -> issue(kt+2) -> sigmoid ->
//             A-frags -> AV-MMA -> STG A (.cs)
// Refill target stage (kt+2)%3 == (kt-1)%3 whose readers all passed this
// tile's sync, so the bottom barrier is gone.
// warps: wm 0..3 (16 S-rows), wn 0..1 (64 S-cols = split-k half for H)
// ---------------------------------------------------------------------------
__global__ __launch_bounds__(256, 2) void fused_attn(
    const fp16* __restrict__ Q, const fp16* __restrict__ K,
    const fp16* __restrict__ V,
    float* __restrict__ Aout, fp16* __restrict__ Hp)
{
    extern __shared__ char smf[];
    constexpr int KT   = 144;               // K/V smem row bytes (64 fp16 + pad)
    constexpr int KSZ  = 128 * KT;          // 18432
    constexpr int BUFS = 2 * KSZ;           // K|V per stage = 36864
    constexpr int NT   = SEQ / 128;         // 16

    const int tid = threadIdx.x, lane = tid & 31, wid = tid >> 5;
    const int wm = wid & 3, wn = wid >> 2;
    const int bh = blockIdx.y, b = bh >> 4, h = bh & 15;
    const int q0 = blockIdx.x * 64;
    const uint32_t sb = smem_u32(smf);
    const int frow = lane & 15, fk8 = (lane >> 4) * 8;

    auto issue = [&](int kt) {
        const uint32_t st = sb + (kt % 3) * BUFS;
        const fp16* kg = K + ((size_t)bh * SEQ + kt * 128) * DK;
        const fp16* vg = V + ((size_t)bh * SEQ + kt * 128) * DK;
        #pragma unroll
        for (int i = 0; i < 4; ++i) {      // 128 rows x 8 chunks each
            const int c = tid + i * 256, row = c >> 3, col = c & 7;
            CP16(st + row * KT + col * 16,       kg + row * DK + col * 8);
            CP16(st + KSZ + row * KT + col * 16, vg + row * DK + col * 8);
        }
        CPCOMMIT();
    };

    // prologue: Q tile staged through stage 2's K-region, then hoisted to regs
    {
        const fp16* Qg = Q + ((size_t)bh * SEQ + q0) * DK;
        #pragma unroll
        for (int i = 0; i < 2; ++i) {      // 64 rows x 8 chunks
            const int c = tid + i * 256, row = c >> 3, col = c & 7;
            CP16(sb + 2 * BUFS + row * KT + col * 16, Qg + row * DK + col * 8);
        }
        CPCOMMIT();
    }
    issue(0);
    issue(1);

    uint32_t qf[4][4];
    CPWAIT(2);                 // Q group done (tiles 0,1 still pending)
    __syncthreads();
    #pragma unroll
    for (int kq = 0; kq < 4; ++kq) {
        const uint32_t off = ((wm * 16 + frow) * 72 + kq * 16 + fk8) * 2;
        LDSM4(qf[kq], sb + 2 * BUFS + off);
    }
    // stage 2 is overwritten by issue(2), which happens after tile-0's sync —
    // by which point every warp has hoisted its Q fragments.

    float accH[8][4] = {};
    float* Abase = Aout + (size_t)bh * SEQ * SEQ;

    // per-lane base for trans V loads: tile order (k0n0, k0n8, k8n0, k8n8)
    const uint32_t vlrow = ((lane >> 4) << 3) + (lane & 7);   // k within 16
    const uint32_t vlcol = ((lane >> 3) & 1) * 16;            // n*2 bytes

    for (int kt = 0; kt < NT; ++kt) {
        if (kt + 1 < NT) CPWAIT(1); else CPWAIT(0);
        __syncthreads();       // single barrier per tile
        const uint32_t st = sb + (kt % 3) * BUFS;

        // ---- S = Q @ K^T (Q fragments from registers) ----
        float accS[8][4] = {};
        #pragma unroll
        for (int kq = 0; kq < 4; ++kq) {
            uint32_t kf[4][4];
            #pragma unroll
            for (int nn = 0; nn < 4; ++nn) {
                const uint32_t off = ((wn * 64 + nn * 16 + frow) * 72 + kq * 16 + fk8) * 2;
                LDSM4(kf[nn], st + off);
            }
            #pragma unroll
            for (int nn = 0; nn < 4; ++nn)
                #pragma unroll
                for (int g = 0; g < 2; ++g)
                    MMA_FP16(accS[nn * 2 + g], qf[kq], kf[nn][g], kf[nn][g + 2]);
        }

        // refill stage (kt+2)%3 = (kt-1)%3: its readers passed this tile's sync
        if (kt + 2 < NT) issue(kt + 2);

        // ---- sigmoid (single-MUFU tanh form) ----
        #pragma unroll
        for (int n8 = 0; n8 < 8; ++n8)
            #pragma unroll
            for (int e = 0; e < 4; ++e)
                accS[n8][e] = sigm(accS[n8][e]);

        // ---- in-register A fragments (acc -> A-frag identity) ----
        uint32_t af[4][4];
        #pragma unroll
        for (int j = 0; j < 4; ++j) {
            af[j][0] = pack2(accS[2 * j][0],     accS[2 * j][1]);
            af[j][1] = pack2(accS[2 * j][2],     accS[2 * j][3]);
            af[j][2] = pack2(accS[2 * j + 1][0], accS[2 * j + 1][1]);
            af[j][3] = pack2(accS[2 * j + 1][2], accS[2 * j + 1][3]);
        }

        // ---- H += S @ V over this warp's 64-row (s) k-slice ----
        #pragma unroll
        for (int j = 0; j < 4; ++j) {
            const uint32_t vbase =
                st + KSZ + (wn * 64 + j * 16 + vlrow) * KT + vlcol;
            uint32_t vf[4][4];
            #pragma unroll
            for (int vn = 0; vn < 4; ++vn)
                LDSM4T(vf[vn], vbase + vn * 32);
            #pragma unroll
            for (int vn = 0; vn < 4; ++vn)
                #pragma unroll
                for (int g = 0; g < 2; ++g)
                    MMA_FP16(accH[vn * 2 + g], af[j], vf[vn][g], vf[vn][g + 2]);
        }

        // ---- store A (streaming; fire-and-forget behind the MMA queue) ----
        {
            const int rl = wm * 16 + (lane >> 2);
            #pragma unroll
            for (int n8 = 0; n8 < 8; ++n8) {
                const int colg = kt * 128 + wn * 64 + n8 * 8 + (lane & 3) * 2;
                __stcs(reinterpret_cast<float2*>(Abase + (size_t)(q0 + rl) * SEQ + colg),
                       make_float2(accS[n8][0], accS[n8][1]));
                __stcs(reinterpret_cast<float2*>(Abase + (size_t)(q0 + rl + 8) * SEQ + colg),
                       make_float2(accS[n8][2], accS[n8][3]));
            }
        }
    }

    // ---- split-k reduce (wn=1 into wn=0) + write Hc fp16 ----
    __syncthreads();
    float* red = reinterpret_cast<float*>(smf);   // 64 x 66 fp32 (tiles dead)
    const int rl = wm * 16 + (lane >> 2);
    if (wn == 1) {
        #pragma unroll
        for (int n8 = 0; n8 < 8; ++n8) {
            const int col = n8 * 8 + (lane & 3) * 2;
            *reinterpret_cast<float2*>(&red[(size_t)rl * 66 + col]) =
                make_float2(accH[n8][0], accH[n8][1]);
            *reinterpret_cast<float2*>(&red[(size_t)(rl + 8) * 66 + col]) =
                make_float2(accH[n8][2], accH[n8][3]);
        }
    }
    __syncthreads();
    if (wn == 0) {
        #pragma unroll
        for (int n8 = 0; n8 < 8; ++n8) {
            const int col = n8 * 8 + (lane & 3) * 2;
            const float2 p0 = *reinterpret_cast<float2*>(&red[(size_t)rl * 66 + col]);
            const float2 p1 = *reinterpret_cast<float2*>(&red[(size_t)(rl + 8) * 66 + col]);
            const size_t off = ((size_t)(b * SEQ + q0 + rl)) * DM + h * DK + col;
            *reinterpret_cast<uint32_t*>(Hp + off) =
                pack2(accH[n8][0] + p0.x, accH[n8][1] + p0.y);
            *reinterpret_cast<uint32_t*>(Hp + off + 8 * DM) =
                pack2(accH[n8][2] + p1.x, accH[n8][3] + p1.y);
        }
    }
}

// ---------------------------------------------------------------------------
extern "C" void kernel_launch(void* const* d_in, const int* in_sizes, int n_in,
                              void* d_out, int out_size)
{
    (void)in_sizes; (void)n_in; (void)out_size;
    const float* Xq = (const float*)d_in[0];
    const float* Xk = (const float*)d_in[1];
    const float* Xv = (const float*)d_in[2];
    const float* Wq = (const float*)d_in[3];
    const float* Wk = (const float*)d_in[4];
    const float* Wv = (const float*)d_in[5];
    const float* Wh = (const float*)d_in[6];
    const float* bh = (const float*)d_in[7];

    float* out  = (float*)d_out;
    float* Aout = out + (size_t)MTOT * DM;

    fp16 *xp, *wp, *qp, *kp, *vp, *hp;
    cudaGetSymbolAddress((void**)&xp, g_X);
    cudaGetSymbolAddress((void**)&wp, g_W);
    cudaGetSymbolAddress((void**)&qp, g_Q);
    cudaGetSymbolAddress((void**)&kp, g_K);
    cudaGetSymbolAddress((void**)&vp, g_Vp);
    cudaGetSymbolAddress((void**)&hp, g_H);

    const size_t WN = (size_t)DM * DM;
    const int smP = 2 * 2 * 128 * 144;             // 73728
    const int smF = 3 * 2 * 128 * 144;             // 110592 (3-stage, 2 CTAs/SM)
    cudaFuncSetAttribute(pgemm_qkv, cudaFuncAttributeMaxDynamicSharedMemorySize, smP);
    cudaFuncSetAttribute(pgemm_out, cudaFuncAttributeMaxDynamicSharedMemorySize, smP);
    cudaFuncSetAttribute(fused_attn, cudaFuncAttributeMaxDynamicSharedMemorySize, smF);

    // prep: W^T fp16 (one launch), X fp16 (one launch)
    wtrans4<<<dim3(32, 32, 4), dim3(32, 8)>>>(Wq, Wk, Wv, Wh, wp);
    cvt_x3<<<dim3(4096, 3), 256>>>((const float4*)Xq, (const float4*)Xk,
                                   (const float4*)Xv, (uint2*)xp);

    // Q/K/V projections in one launch (all per-head fp16)
    pgemm_qkv<<<dim3(DM / 128, MTOT / 128, 3), 256, smP>>>(xp, wp, qp, kp, vp);

    // fused attention (writes A fp32 and Hc fp16); Q-tile 64 -> grid (32, 32)
    fused_attn<<<dim3(SEQ / 64, NBH), 256, smF>>>(qp, kp, vp, Aout, hp);

    // output projection (+bias)
    pgemm_out<<<dim3(DM / 128, MTOT / 128), 256, smP>>>(hp, wp + 3 * WN, out, bh);
}